// round 15
// baseline (speedup 1.0000x reference)
#include <cuda_runtime.h>
#include <cstdint>

// Problem constants (fixed by the dataset)
#define NN 500000
#define GG 1000

// ---------------------------------------------------------------------------
// Scratch (separate device symbols — scatters compile to 32 regs / ~87% occ).
// g_deg[n]: lo32 = deg_in, hi32 = deg_out (packed u64).
// ---------------------------------------------------------------------------
__device__ unsigned long long g_deg [NN];
__device__ float              g_agg1[NN];   // layer-1 scalar aggregation
__device__ float              g_t   [NN];   // s * isi * iso (layer-2 propagand)
__device__ float              g_A   [NN];   // layer-2 scalar aggregation
__device__ float              g_S   [GG];   // pooled scalar sum per graph
__device__ float              g_cnt [GG];   // nodes per graph

#define ONE_IN  1ull
#define ONE_OUT (1ull << 32)

__device__ __forceinline__ void red_f32(float* p, float v) {
    asm volatile("red.global.add.f32 [%0], %1;" :: "l"(p), "f"(v) : "memory");
}
__device__ __forceinline__ void red_u64(unsigned long long* p, unsigned long long v) {
    asm volatile("red.global.add.u64 [%0], %1;" :: "l"(p), "l"(v) : "memory");
}

// ---------------------------------------------------------------------------
// K1: degree counting, packed u64. 8 edges / thread, flat one-chunk-per-thread.
//     PDL: index loads (input-only) before the dependency sync (memset).
// ---------------------------------------------------------------------------
__global__ void k_deg(const int* __restrict__ src, const int* __restrict__ dst, int E) {
    int i = blockIdx.x * blockDim.x + threadIdx.x;
    int base = i << 3;
    if (base + 7 < E) {
        int4 s0 = *reinterpret_cast<const int4*>(src + base);
        int4 s1 = *reinterpret_cast<const int4*>(src + base + 4);
        int4 d0 = *reinterpret_cast<const int4*>(dst + base);
        int4 d1 = *reinterpret_cast<const int4*>(dst + base + 4);
        cudaGridDependencySynchronize();   // wait: g_deg memset visible
        red_u64(&g_deg[s0.x], ONE_OUT); red_u64(&g_deg[s0.y], ONE_OUT);
        red_u64(&g_deg[s0.z], ONE_OUT); red_u64(&g_deg[s0.w], ONE_OUT);
        red_u64(&g_deg[s1.x], ONE_OUT); red_u64(&g_deg[s1.y], ONE_OUT);
        red_u64(&g_deg[s1.z], ONE_OUT); red_u64(&g_deg[s1.w], ONE_OUT);
        red_u64(&g_deg[d0.x], ONE_IN);  red_u64(&g_deg[d0.y], ONE_IN);
        red_u64(&g_deg[d0.z], ONE_IN);  red_u64(&g_deg[d0.w], ONE_IN);
        red_u64(&g_deg[d1.x], ONE_IN);  red_u64(&g_deg[d1.y], ONE_IN);
        red_u64(&g_deg[d1.z], ONE_IN);  red_u64(&g_deg[d1.w], ONE_IN);
    } else {
        cudaGridDependencySynchronize();
        for (int e = base; e < E; ++e) {
            red_u64(&g_deg[src[e]], ONE_OUT);
            red_u64(&g_deg[dst[e]], ONE_IN);
        }
    }
}

// ---------------------------------------------------------------------------
// K2: layer-1 scatter, x0 inline. 8 edges / thread.
// ---------------------------------------------------------------------------
__device__ __forceinline__ float x0_of(unsigned long long p) {
    float di = (float)(unsigned)p;
    float dq = (float)(unsigned)(p >> 32);
    return di * rsqrtf(fmaxf(dq, 1.0f));
}

__global__ void k_scatter1(const int* __restrict__ src, const int* __restrict__ dst, int E) {
    int i = blockIdx.x * blockDim.x + threadIdx.x;
    int base = i << 3;
    if (base + 7 < E) {
        int4 s0 = *reinterpret_cast<const int4*>(src + base);
        int4 s1 = *reinterpret_cast<const int4*>(src + base + 4);
        int4 d0 = *reinterpret_cast<const int4*>(dst + base);
        int4 d1 = *reinterpret_cast<const int4*>(dst + base + 4);
        cudaGridDependencySynchronize();   // wait: k_deg complete
        float v0 = x0_of(__ldg(&g_deg[s0.x]));
        float v1 = x0_of(__ldg(&g_deg[s0.y]));
        float v2 = x0_of(__ldg(&g_deg[s0.z]));
        float v3 = x0_of(__ldg(&g_deg[s0.w]));
        float v4 = x0_of(__ldg(&g_deg[s1.x]));
        float v5 = x0_of(__ldg(&g_deg[s1.y]));
        float v6 = x0_of(__ldg(&g_deg[s1.z]));
        float v7 = x0_of(__ldg(&g_deg[s1.w]));
        red_f32(&g_agg1[d0.x], v0); red_f32(&g_agg1[d0.y], v1);
        red_f32(&g_agg1[d0.z], v2); red_f32(&g_agg1[d0.w], v3);
        red_f32(&g_agg1[d1.x], v4); red_f32(&g_agg1[d1.y], v5);
        red_f32(&g_agg1[d1.z], v6); red_f32(&g_agg1[d1.w], v7);
    } else {
        cudaGridDependencySynchronize();
        for (int e = base; e < E; ++e)
            red_f32(&g_agg1[dst[e]], x0_of(__ldg(&g_deg[src[e]])));
    }
}

// ---------------------------------------------------------------------------
// K3: t = agg1 * isi * iso — vectorized 4 nodes/thread.
//     Zeroes A/S/cnt BEFORE the dependency sync (independent of upstream).
// ---------------------------------------------------------------------------
__global__ void k_t(int N) {
    int i = blockIdx.x * blockDim.x + threadIdx.x;
    int base = i << 2;
    if (i < GG) { g_S[i] = 0.0f; g_cnt[i] = 0.0f; }       // untouched upstream
    if (base + 3 < N) {                                   // untouched upstream
        *reinterpret_cast<float4*>(g_A + base) = make_float4(0.f, 0.f, 0.f, 0.f);
    } else {
        for (int n = base; n < N; ++n) g_A[n] = 0.0f;
    }
    cudaGridDependencySynchronize();                      // wait: k_scatter1 done
    if (base + 3 < N) {
        ulonglong2 p01 = *reinterpret_cast<const ulonglong2*>(g_deg + base);
        ulonglong2 p23 = *reinterpret_cast<const ulonglong2*>(g_deg + base + 2);
        float4 a = *reinterpret_cast<const float4*>(g_agg1 + base);
        float4 r;
        r.x = a.x * rsqrtf(fmaxf((float)(unsigned)p01.x, 1.0f)) * rsqrtf(fmaxf((float)(unsigned)(p01.x >> 32), 1.0f));
        r.y = a.y * rsqrtf(fmaxf((float)(unsigned)p01.y, 1.0f)) * rsqrtf(fmaxf((float)(unsigned)(p01.y >> 32), 1.0f));
        r.z = a.z * rsqrtf(fmaxf((float)(unsigned)p23.x, 1.0f)) * rsqrtf(fmaxf((float)(unsigned)(p23.x >> 32), 1.0f));
        r.w = a.w * rsqrtf(fmaxf((float)(unsigned)p23.y, 1.0f)) * rsqrtf(fmaxf((float)(unsigned)(p23.y >> 32), 1.0f));
        *reinterpret_cast<float4*>(g_t + base) = r;
    } else {
        for (int n = base; n < N; ++n) {
            unsigned long long p = g_deg[n];
            g_t[n] = g_agg1[n]
                   * rsqrtf(fmaxf((float)(unsigned)p, 1.0f))
                   * rsqrtf(fmaxf((float)(unsigned)(p >> 32), 1.0f));
        }
    }
}

// ---------------------------------------------------------------------------
// K4: layer-2 scalar scatter  A[dst] += t[src]. 8 edges / thread.
// ---------------------------------------------------------------------------
__global__ void k_scatter2(const int* __restrict__ src, const int* __restrict__ dst, int E) {
    int i = blockIdx.x * blockDim.x + threadIdx.x;
    int base = i << 3;
    if (base + 7 < E) {
        int4 s0 = *reinterpret_cast<const int4*>(src + base);
        int4 s1 = *reinterpret_cast<const int4*>(src + base + 4);
        int4 d0 = *reinterpret_cast<const int4*>(dst + base);
        int4 d1 = *reinterpret_cast<const int4*>(dst + base + 4);
        cudaGridDependencySynchronize();   // wait: k_t complete (t and A=0)
        float v0 = __ldg(&g_t[s0.x]);
        float v1 = __ldg(&g_t[s0.y]);
        float v2 = __ldg(&g_t[s0.z]);
        float v3 = __ldg(&g_t[s0.w]);
        float v4 = __ldg(&g_t[s1.x]);
        float v5 = __ldg(&g_t[s1.y]);
        float v6 = __ldg(&g_t[s1.z]);
        float v7 = __ldg(&g_t[s1.w]);
        red_f32(&g_A[d0.x], v0); red_f32(&g_A[d0.y], v1);
        red_f32(&g_A[d0.z], v2); red_f32(&g_A[d0.w], v3);
        red_f32(&g_A[d1.x], v4); red_f32(&g_A[d1.y], v5);
        red_f32(&g_A[d1.z], v6); red_f32(&g_A[d1.w], v7);
    } else {
        cudaGridDependencySynchronize();
        for (int e = base; e < E; ++e)
            red_f32(&g_A[dst[e]], __ldg(&g_t[src[e]]));
    }
}

// ---------------------------------------------------------------------------
// K5: pooling, 4 nodes/thread (128-node warp spans, sorted gid).
//     Uniform warp (~74%): 1 shuffle tree + 2 REDs for 128 nodes.
//     Boundary warp: per-thread run compression (<=3 runs in a sorted 4-tuple).
// ---------------------------------------------------------------------------
__global__ void k_pool(const int* __restrict__ gid, int N) {
    int i = blockIdx.x * blockDim.x + threadIdx.x;
    int base = i << 2;
    bool full = (base + 3 < N);
    int4 g4 = make_int4(-1, -1, -1, -1);
    if (full) g4 = *reinterpret_cast<const int4*>(gid + base);   // input, pre-sync
    cudaGridDependencySynchronize();       // wait: k_scatter2 complete

    float u0 = 0.f, u1 = 0.f, u2 = 0.f, u3 = 0.f;
    if (full) {
        ulonglong2 p01 = *reinterpret_cast<const ulonglong2*>(g_deg + base);
        ulonglong2 p23 = *reinterpret_cast<const ulonglong2*>(g_deg + base + 2);
        float4 a = *reinterpret_cast<const float4*>(g_A + base);
        u0 = a.x * rsqrtf(fmaxf((float)(unsigned)p01.x, 1.0f));
        u1 = a.y * rsqrtf(fmaxf((float)(unsigned)p01.y, 1.0f));
        u2 = a.z * rsqrtf(fmaxf((float)(unsigned)p23.x, 1.0f));
        u3 = a.w * rsqrtf(fmaxf((float)(unsigned)p23.y, 1.0f));
    }

    int  g0  = __shfl_sync(0xffffffffu, g4.x, 0);
    bool uni = __all_sync(0xffffffffu, full && (g4.x == g0) && (g4.w == g0));

    if (uni) {
        float u = (u0 + u1) + (u2 + u3);
#pragma unroll
        for (int o = 16; o > 0; o >>= 1)
            u += __shfl_xor_sync(0xffffffffu, u, o);
        if ((threadIdx.x & 31) == 0) {
            red_f32(&g_S[g0], u);
            red_f32(&g_cnt[g0], 128.0f);
        }
    } else if (full) {
        // sorted 4-tuple -> run compression (usually 1 run, rarely 2-3)
        int   cg = g4.x;  float s = u0;  float c = 1.0f;
        if (g4.y == cg) { s += u1; c += 1.0f; }
        else { red_f32(&g_S[cg], s); red_f32(&g_cnt[cg], c); cg = g4.y; s = u1; c = 1.0f; }
        if (g4.z == cg) { s += u2; c += 1.0f; }
        else { red_f32(&g_S[cg], s); red_f32(&g_cnt[cg], c); cg = g4.z; s = u2; c = 1.0f; }
        if (g4.w == cg) { s += u3; c += 1.0f; }
        else { red_f32(&g_S[cg], s); red_f32(&g_cnt[cg], c); cg = g4.w; s = u3; c = 1.0f; }
        red_f32(&g_S[cg], s); red_f32(&g_cnt[cg], c);
    } else {
        // tail: scalar per node
        for (int n = base; n < N; ++n) {
            unsigned long long p = g_deg[n];
            float u = g_A[n] * rsqrtf(fmaxf((float)(unsigned)p, 1.0f));
            int g = gid[n];
            red_f32(&g_S[g], u);
            red_f32(&g_cnt[g], 1.0f);
        }
    }
}

// ---------------------------------------------------------------------------
// K6: out[g][c] = (S_g/max(cnt_g,1)) * rW_c.  rw GEMV before sync (inputs only).
// ---------------------------------------------------------------------------
__global__ void k_final(const float* __restrict__ W1, const float* __restrict__ W2,
                        const float* __restrict__ Wlast, float* __restrict__ out, int G) {
    int t = blockIdx.x * blockDim.x + threadIdx.x;
    int c = t & 7;
    float rw = 0.0f;
#pragma unroll
    for (int k = 0; k < 8; ++k) {
        float q = 0.0f;
#pragma unroll
        for (int j = 0; j < 8; ++j)
            q += fmaxf(__ldg(&W1[j]), 0.0f) * __ldg(&W2[j * 8 + k]);
        rw += fmaxf(q, 0.0f) * __ldg(&Wlast[k * 8 + c]);
    }
    cudaGridDependencySynchronize();       // wait: k_pool complete
    if (t >= G * 8) return;
    int g = t >> 3;
    out[t] = (g_S[g] / fmaxf(g_cnt[g], 1.0f)) * rw;
}

// ---------------------------------------------------------------------------
// kernel_launch — proven-best PDL chain; k_pool now 4 nodes/thread.
// Inputs (metadata order): W1[8], W2[64], Wlast[64], src[E], dst[E], graph_ids[N]
// Output: G*C float32
// ---------------------------------------------------------------------------
extern "C" void kernel_launch(void* const* d_in, const int* in_sizes, int n_in,
                              void* d_out, int out_size) {
    const float* W1    = (const float*)d_in[0];
    const float* W2    = (const float*)d_in[1];
    const float* Wlast = (const float*)d_in[2];
    const int*   src   = (const int*)d_in[3];
    const int*   dst   = (const int*)d_in[4];
    const int*   gid   = (const int*)d_in[5];

    int E = in_sizes[3];
    int N = in_sizes[5];
    int G = out_size / 8;
    float* out = (float*)d_out;

    void *pdeg, *pa1;
    cudaGetSymbolAddress(&pdeg, g_deg);
    cudaGetSymbolAddress(&pa1,  g_agg1);
    cudaMemsetAsync(pdeg, 0, (size_t)N * sizeof(unsigned long long));
    cudaMemsetAsync(pa1,  0, (size_t)N * sizeof(float));

    const int TB = 256;
    int nE8 = (E + 7) / 8;
    unsigned gE8 = (unsigned)((nE8 + TB - 1) / TB);
    unsigned gN4 = (unsigned)(((N + 3) / 4 + TB - 1) / TB);
    unsigned gF  = (unsigned)((G * 8 + TB - 1) / TB);

    cudaLaunchAttribute attr[1];
    attr[0].id = cudaLaunchAttributeProgrammaticStreamSerialization;
    attr[0].val.programmaticStreamSerializationAllowed = 1;

    cudaLaunchConfig_t cfg{};
    cfg.blockDim = {TB, 1, 1};
    cfg.attrs = attr;
    cfg.numAttrs = 1;
    cfg.stream = 0;

    cfg.gridDim = {gE8, 1, 1};
    cudaLaunchKernelEx(&cfg, k_deg, src, dst, E);
    cudaLaunchKernelEx(&cfg, k_scatter1, src, dst, E);
    cfg.gridDim = {gN4, 1, 1};
    cudaLaunchKernelEx(&cfg, k_t, N);
    cfg.gridDim = {gE8, 1, 1};
    cudaLaunchKernelEx(&cfg, k_scatter2, src, dst, E);
    cfg.gridDim = {gN4, 1, 1};
    cudaLaunchKernelEx(&cfg, k_pool, gid, N);
    cfg.gridDim = {gF, 1, 1};
    cudaLaunchKernelEx(&cfg, k_final, W1, W2, Wlast, out, G);
}

// round 16
// speedup vs baseline: 1.0079x; 1.0079x over previous
#include <cuda_runtime.h>
#include <cstdint>

// Problem constants (fixed by the dataset)
#define NN 500000
#define GG 1000

// ---------------------------------------------------------------------------
// Scratch (separate device symbols — scatters compile to 32 regs / ~87% occ).
// g_deg[n]: lo32 = deg_in, hi32 = deg_out (packed u64).
// ---------------------------------------------------------------------------
__device__ unsigned long long g_deg [NN];
__device__ float              g_agg1[NN];   // layer-1 scalar aggregation
__device__ float              g_t   [NN];   // s * isi * iso (layer-2 propagand)
__device__ float              g_A   [NN];   // layer-2 scalar aggregation
__device__ float              g_S   [GG];   // pooled scalar sum per graph
__device__ float              g_cnt [GG];   // nodes per graph

#define ONE_IN  1ull
#define ONE_OUT (1ull << 32)

__device__ __forceinline__ void red_f32(float* p, float v) {
    asm volatile("red.global.add.f32 [%0], %1;" :: "l"(p), "f"(v) : "memory");
}
__device__ __forceinline__ void red_u64(unsigned long long* p, unsigned long long v) {
    asm volatile("red.global.add.u64 [%0], %1;" :: "l"(p), "l"(v) : "memory");
}

// ---------------------------------------------------------------------------
// K1: degree counting, packed u64. 8 edges / thread, flat one-chunk-per-thread.
//     PDL: index loads (input-only) before the dependency sync (memset).
// ---------------------------------------------------------------------------
__global__ void k_deg(const int* __restrict__ src, const int* __restrict__ dst, int E) {
    int i = blockIdx.x * blockDim.x + threadIdx.x;
    int base = i << 3;
    if (base + 7 < E) {
        int4 s0 = *reinterpret_cast<const int4*>(src + base);
        int4 s1 = *reinterpret_cast<const int4*>(src + base + 4);
        int4 d0 = *reinterpret_cast<const int4*>(dst + base);
        int4 d1 = *reinterpret_cast<const int4*>(dst + base + 4);
        cudaGridDependencySynchronize();   // wait: g_deg memset visible
        red_u64(&g_deg[s0.x], ONE_OUT); red_u64(&g_deg[s0.y], ONE_OUT);
        red_u64(&g_deg[s0.z], ONE_OUT); red_u64(&g_deg[s0.w], ONE_OUT);
        red_u64(&g_deg[s1.x], ONE_OUT); red_u64(&g_deg[s1.y], ONE_OUT);
        red_u64(&g_deg[s1.z], ONE_OUT); red_u64(&g_deg[s1.w], ONE_OUT);
        red_u64(&g_deg[d0.x], ONE_IN);  red_u64(&g_deg[d0.y], ONE_IN);
        red_u64(&g_deg[d0.z], ONE_IN);  red_u64(&g_deg[d0.w], ONE_IN);
        red_u64(&g_deg[d1.x], ONE_IN);  red_u64(&g_deg[d1.y], ONE_IN);
        red_u64(&g_deg[d1.z], ONE_IN);  red_u64(&g_deg[d1.w], ONE_IN);
    } else {
        cudaGridDependencySynchronize();
        for (int e = base; e < E; ++e) {
            red_u64(&g_deg[src[e]], ONE_OUT);
            red_u64(&g_deg[dst[e]], ONE_IN);
        }
    }
}

// ---------------------------------------------------------------------------
// K2: layer-1 scatter, x0 inline. 8 edges / thread.
// ---------------------------------------------------------------------------
__device__ __forceinline__ float x0_of(unsigned long long p) {
    float di = (float)(unsigned)p;
    float dq = (float)(unsigned)(p >> 32);
    return di * rsqrtf(fmaxf(dq, 1.0f));
}

__global__ void k_scatter1(const int* __restrict__ src, const int* __restrict__ dst, int E) {
    int i = blockIdx.x * blockDim.x + threadIdx.x;
    int base = i << 3;
    if (base + 7 < E) {
        int4 s0 = *reinterpret_cast<const int4*>(src + base);
        int4 s1 = *reinterpret_cast<const int4*>(src + base + 4);
        int4 d0 = *reinterpret_cast<const int4*>(dst + base);
        int4 d1 = *reinterpret_cast<const int4*>(dst + base + 4);
        cudaGridDependencySynchronize();   // wait: k_deg complete
        float v0 = x0_of(__ldg(&g_deg[s0.x]));
        float v1 = x0_of(__ldg(&g_deg[s0.y]));
        float v2 = x0_of(__ldg(&g_deg[s0.z]));
        float v3 = x0_of(__ldg(&g_deg[s0.w]));
        float v4 = x0_of(__ldg(&g_deg[s1.x]));
        float v5 = x0_of(__ldg(&g_deg[s1.y]));
        float v6 = x0_of(__ldg(&g_deg[s1.z]));
        float v7 = x0_of(__ldg(&g_deg[s1.w]));
        red_f32(&g_agg1[d0.x], v0); red_f32(&g_agg1[d0.y], v1);
        red_f32(&g_agg1[d0.z], v2); red_f32(&g_agg1[d0.w], v3);
        red_f32(&g_agg1[d1.x], v4); red_f32(&g_agg1[d1.y], v5);
        red_f32(&g_agg1[d1.z], v6); red_f32(&g_agg1[d1.w], v7);
    } else {
        cudaGridDependencySynchronize();
        for (int e = base; e < E; ++e)
            red_f32(&g_agg1[dst[e]], x0_of(__ldg(&g_deg[src[e]])));
    }
}

// ---------------------------------------------------------------------------
// K3: t = agg1 * isi * iso — vectorized 4 nodes/thread.
//     Zeroes A/S/cnt BEFORE the dependency sync (independent of upstream).
// ---------------------------------------------------------------------------
__global__ void k_t(int N) {
    int i = blockIdx.x * blockDim.x + threadIdx.x;
    int base = i << 2;
    if (i < GG) { g_S[i] = 0.0f; g_cnt[i] = 0.0f; }       // untouched upstream
    if (base + 3 < N) {                                   // untouched upstream
        *reinterpret_cast<float4*>(g_A + base) = make_float4(0.f, 0.f, 0.f, 0.f);
    } else {
        for (int n = base; n < N; ++n) g_A[n] = 0.0f;
    }
    cudaGridDependencySynchronize();                      // wait: k_scatter1 done
    if (base + 3 < N) {
        ulonglong2 p01 = *reinterpret_cast<const ulonglong2*>(g_deg + base);
        ulonglong2 p23 = *reinterpret_cast<const ulonglong2*>(g_deg + base + 2);
        float4 a = *reinterpret_cast<const float4*>(g_agg1 + base);
        float4 r;
        r.x = a.x * rsqrtf(fmaxf((float)(unsigned)p01.x, 1.0f)) * rsqrtf(fmaxf((float)(unsigned)(p01.x >> 32), 1.0f));
        r.y = a.y * rsqrtf(fmaxf((float)(unsigned)p01.y, 1.0f)) * rsqrtf(fmaxf((float)(unsigned)(p01.y >> 32), 1.0f));
        r.z = a.z * rsqrtf(fmaxf((float)(unsigned)p23.x, 1.0f)) * rsqrtf(fmaxf((float)(unsigned)(p23.x >> 32), 1.0f));
        r.w = a.w * rsqrtf(fmaxf((float)(unsigned)p23.y, 1.0f)) * rsqrtf(fmaxf((float)(unsigned)(p23.y >> 32), 1.0f));
        *reinterpret_cast<float4*>(g_t + base) = r;
    } else {
        for (int n = base; n < N; ++n) {
            unsigned long long p = g_deg[n];
            g_t[n] = g_agg1[n]
                   * rsqrtf(fmaxf((float)(unsigned)p, 1.0f))
                   * rsqrtf(fmaxf((float)(unsigned)(p >> 32), 1.0f));
        }
    }
}

// ---------------------------------------------------------------------------
// K4: layer-2 scalar scatter  A[dst] += t[src]. 8 edges / thread.
// ---------------------------------------------------------------------------
__global__ void k_scatter2(const int* __restrict__ src, const int* __restrict__ dst, int E) {
    int i = blockIdx.x * blockDim.x + threadIdx.x;
    int base = i << 3;
    if (base + 7 < E) {
        int4 s0 = *reinterpret_cast<const int4*>(src + base);
        int4 s1 = *reinterpret_cast<const int4*>(src + base + 4);
        int4 d0 = *reinterpret_cast<const int4*>(dst + base);
        int4 d1 = *reinterpret_cast<const int4*>(dst + base + 4);
        cudaGridDependencySynchronize();   // wait: k_t complete (t and A=0)
        float v0 = __ldg(&g_t[s0.x]);
        float v1 = __ldg(&g_t[s0.y]);
        float v2 = __ldg(&g_t[s0.z]);
        float v3 = __ldg(&g_t[s0.w]);
        float v4 = __ldg(&g_t[s1.x]);
        float v5 = __ldg(&g_t[s1.y]);
        float v6 = __ldg(&g_t[s1.z]);
        float v7 = __ldg(&g_t[s1.w]);
        red_f32(&g_A[d0.x], v0); red_f32(&g_A[d0.y], v1);
        red_f32(&g_A[d0.z], v2); red_f32(&g_A[d0.w], v3);
        red_f32(&g_A[d1.x], v4); red_f32(&g_A[d1.y], v5);
        red_f32(&g_A[d1.z], v6); red_f32(&g_A[d1.w], v7);
    } else {
        cudaGridDependencySynchronize();
        for (int e = base; e < E; ++e)
            red_f32(&g_A[dst[e]], __ldg(&g_t[src[e]]));
    }
}

// ---------------------------------------------------------------------------
// K5: pooling, 4 nodes/thread (128-node warp spans, sorted gid).
//     Uniform warp (~74%): 1 shuffle tree + 2 REDs for 128 nodes.
//     Boundary warp: per-thread run compression (<=3 runs in a sorted 4-tuple).
// ---------------------------------------------------------------------------
__global__ void k_pool(const int* __restrict__ gid, int N) {
    int i = blockIdx.x * blockDim.x + threadIdx.x;
    int base = i << 2;
    bool full = (base + 3 < N);
    int4 g4 = make_int4(-1, -1, -1, -1);
    if (full) g4 = *reinterpret_cast<const int4*>(gid + base);   // input, pre-sync
    cudaGridDependencySynchronize();       // wait: k_scatter2 complete

    float u0 = 0.f, u1 = 0.f, u2 = 0.f, u3 = 0.f;
    if (full) {
        ulonglong2 p01 = *reinterpret_cast<const ulonglong2*>(g_deg + base);
        ulonglong2 p23 = *reinterpret_cast<const ulonglong2*>(g_deg + base + 2);
        float4 a = *reinterpret_cast<const float4*>(g_A + base);
        u0 = a.x * rsqrtf(fmaxf((float)(unsigned)p01.x, 1.0f));
        u1 = a.y * rsqrtf(fmaxf((float)(unsigned)p01.y, 1.0f));
        u2 = a.z * rsqrtf(fmaxf((float)(unsigned)p23.x, 1.0f));
        u3 = a.w * rsqrtf(fmaxf((float)(unsigned)p23.y, 1.0f));
    }

    int  g0  = __shfl_sync(0xffffffffu, g4.x, 0);
    bool uni = __all_sync(0xffffffffu, full && (g4.x == g0) && (g4.w == g0));

    if (uni) {
        float u = (u0 + u1) + (u2 + u3);
#pragma unroll
        for (int o = 16; o > 0; o >>= 1)
            u += __shfl_xor_sync(0xffffffffu, u, o);
        if ((threadIdx.x & 31) == 0) {
            red_f32(&g_S[g0], u);
            red_f32(&g_cnt[g0], 128.0f);
        }
    } else if (full) {
        // sorted 4-tuple -> run compression (usually 1 run, rarely 2-3)
        int   cg = g4.x;  float s = u0;  float c = 1.0f;
        if (g4.y == cg) { s += u1; c += 1.0f; }
        else { red_f32(&g_S[cg], s); red_f32(&g_cnt[cg], c); cg = g4.y; s = u1; c = 1.0f; }
        if (g4.z == cg) { s += u2; c += 1.0f; }
        else { red_f32(&g_S[cg], s); red_f32(&g_cnt[cg], c); cg = g4.z; s = u2; c = 1.0f; }
        if (g4.w == cg) { s += u3; c += 1.0f; }
        else { red_f32(&g_S[cg], s); red_f32(&g_cnt[cg], c); cg = g4.w; s = u3; c = 1.0f; }
        red_f32(&g_S[cg], s); red_f32(&g_cnt[cg], c);
    } else {
        // tail: scalar per node
        for (int n = base; n < N; ++n) {
            unsigned long long p = g_deg[n];
            float u = g_A[n] * rsqrtf(fmaxf((float)(unsigned)p, 1.0f));
            int g = gid[n];
            red_f32(&g_S[g], u);
            red_f32(&g_cnt[g], 1.0f);
        }
    }
}

// ---------------------------------------------------------------------------
// K6: out[g][c] = (S_g/max(cnt_g,1)) * rW_c.  rw GEMV before sync (inputs only).
// ---------------------------------------------------------------------------
__global__ void k_final(const float* __restrict__ W1, const float* __restrict__ W2,
                        const float* __restrict__ Wlast, float* __restrict__ out, int G) {
    int t = blockIdx.x * blockDim.x + threadIdx.x;
    int c = t & 7;
    float rw = 0.0f;
#pragma unroll
    for (int k = 0; k < 8; ++k) {
        float q = 0.0f;
#pragma unroll
        for (int j = 0; j < 8; ++j)
            q += fmaxf(__ldg(&W1[j]), 0.0f) * __ldg(&W2[j * 8 + k]);
        rw += fmaxf(q, 0.0f) * __ldg(&Wlast[k * 8 + c]);
    }
    cudaGridDependencySynchronize();       // wait: k_pool complete
    if (t >= G * 8) return;
    int g = t >> 3;
    out[t] = (g_S[g] / fmaxf(g_cnt[g], 1.0f)) * rw;
}

// ---------------------------------------------------------------------------
// kernel_launch — final configuration: PDL chain, TB=256, flat oversubscribed
// grids, dense scalar scratch arrays, vectorized node kernels.
// Inputs (metadata order): W1[8], W2[64], Wlast[64], src[E], dst[E], graph_ids[N]
// Output: G*C float32
// ---------------------------------------------------------------------------
extern "C" void kernel_launch(void* const* d_in, const int* in_sizes, int n_in,
                              void* d_out, int out_size) {
    const float* W1    = (const float*)d_in[0];
    const float* W2    = (const float*)d_in[1];
    const float* Wlast = (const float*)d_in[2];
    const int*   src   = (const int*)d_in[3];
    const int*   dst   = (const int*)d_in[4];
    const int*   gid   = (const int*)d_in[5];

    int E = in_sizes[3];
    int N = in_sizes[5];
    int G = out_size / 8;
    float* out = (float*)d_out;

    void *pdeg, *pa1;
    cudaGetSymbolAddress(&pdeg, g_deg);
    cudaGetSymbolAddress(&pa1,  g_agg1);
    cudaMemsetAsync(pdeg, 0, (size_t)N * sizeof(unsigned long long));
    cudaMemsetAsync(pa1,  0, (size_t)N * sizeof(float));

    const int TB = 256;
    int nE8 = (E + 7) / 8;
    unsigned gE8 = (unsigned)((nE8 + TB - 1) / TB);
    unsigned gN4 = (unsigned)(((N + 3) / 4 + TB - 1) / TB);
    unsigned gF  = (unsigned)((G * 8 + TB - 1) / TB);

    cudaLaunchAttribute attr[1];
    attr[0].id = cudaLaunchAttributeProgrammaticStreamSerialization;
    attr[0].val.programmaticStreamSerializationAllowed = 1;

    cudaLaunchConfig_t cfg{};
    cfg.blockDim = {TB, 1, 1};
    cfg.attrs = attr;
    cfg.numAttrs = 1;
    cfg.stream = 0;

    cfg.gridDim = {gE8, 1, 1};
    cudaLaunchKernelEx(&cfg, k_deg, src, dst, E);
    cudaLaunchKernelEx(&cfg, k_scatter1, src, dst, E);
    cfg.gridDim = {gN4, 1, 1};
    cudaLaunchKernelEx(&cfg, k_t, N);
    cfg.gridDim = {gE8, 1, 1};
    cudaLaunchKernelEx(&cfg, k_scatter2, src, dst, E);
    cfg.gridDim = {gN4, 1, 1};
    cudaLaunchKernelEx(&cfg, k_pool, gid, N);
    cfg.gridDim = {gF, 1, 1};
    cudaLaunchKernelEx(&cfg, k_final, W1, W2, Wlast, out, G);
}

// round 17
// speedup vs baseline: 1.0132x; 1.0053x over previous
#include <cuda_runtime.h>
#include <cstdint>

// Problem constants (fixed by the dataset)
#define NN 500000
#define GG 1000

// ---------------------------------------------------------------------------
// Scratch (separate device symbols — scatters compile to 32 regs / ~87% occ).
// g_deg[n]: lo32 = deg_in, hi32 = deg_out (packed u64).
// g_pool[g]: x = S (pooled sum), y = cnt (node count) — red.v2 target.
// ---------------------------------------------------------------------------
__device__ unsigned long long g_deg [NN];
__device__ float              g_agg1[NN];   // layer-1 scalar aggregation
__device__ float              g_t   [NN];   // s * isi * iso (layer-2 propagand)
__device__ float              g_A   [NN];   // layer-2 scalar aggregation
__device__ float2             g_pool[GG];   // {S, cnt} per graph

#define ONE_IN  1ull
#define ONE_OUT (1ull << 32)

__device__ __forceinline__ void red_f32(float* p, float v) {
    asm volatile("red.global.add.f32 [%0], %1;" :: "l"(p), "f"(v) : "memory");
}
__device__ __forceinline__ void red_u64(unsigned long long* p, unsigned long long v) {
    asm volatile("red.global.add.u64 [%0], %1;" :: "l"(p), "l"(v) : "memory");
}
__device__ __forceinline__ void red_v2(float2* p, float a, float b) {
    asm volatile("red.global.add.v2.f32 [%0], {%1, %2};"
                 :: "l"(p), "f"(a), "f"(b) : "memory");
}

// ---------------------------------------------------------------------------
// K1: degree counting, packed u64. 8 edges / thread, flat one-chunk-per-thread.
//     Pre-sync: index loads (inputs) + zero g_agg1 (untouched by the memset,
//     untouched upstream; ordered before scatter1 by the kernel boundary).
// ---------------------------------------------------------------------------
__global__ void k_deg(const int* __restrict__ src, const int* __restrict__ dst,
                      int E, int N) {
    int i = blockIdx.x * blockDim.x + threadIdx.x;
    int zb = i << 2;                       // zero agg1: first ceil(N/4) threads
    if (zb < N) {
        if (zb + 3 < N) {
            *reinterpret_cast<float4*>(g_agg1 + zb) = make_float4(0.f, 0.f, 0.f, 0.f);
        } else {
            for (int n = zb; n < N; ++n) g_agg1[n] = 0.0f;
        }
    }
    int base = i << 3;
    if (base + 7 < E) {
        int4 s0 = *reinterpret_cast<const int4*>(src + base);
        int4 s1 = *reinterpret_cast<const int4*>(src + base + 4);
        int4 d0 = *reinterpret_cast<const int4*>(dst + base);
        int4 d1 = *reinterpret_cast<const int4*>(dst + base + 4);
        cudaGridDependencySynchronize();   // wait: g_deg memset visible
        red_u64(&g_deg[s0.x], ONE_OUT); red_u64(&g_deg[s0.y], ONE_OUT);
        red_u64(&g_deg[s0.z], ONE_OUT); red_u64(&g_deg[s0.w], ONE_OUT);
        red_u64(&g_deg[s1.x], ONE_OUT); red_u64(&g_deg[s1.y], ONE_OUT);
        red_u64(&g_deg[s1.z], ONE_OUT); red_u64(&g_deg[s1.w], ONE_OUT);
        red_u64(&g_deg[d0.x], ONE_IN);  red_u64(&g_deg[d0.y], ONE_IN);
        red_u64(&g_deg[d0.z], ONE_IN);  red_u64(&g_deg[d0.w], ONE_IN);
        red_u64(&g_deg[d1.x], ONE_IN);  red_u64(&g_deg[d1.y], ONE_IN);
        red_u64(&g_deg[d1.z], ONE_IN);  red_u64(&g_deg[d1.w], ONE_IN);
    } else {
        cudaGridDependencySynchronize();
        for (int e = base; e < E; ++e) {
            red_u64(&g_deg[src[e]], ONE_OUT);
            red_u64(&g_deg[dst[e]], ONE_IN);
        }
    }
}

// ---------------------------------------------------------------------------
// K2: layer-1 scatter, x0 inline. 8 edges / thread. (Body frozen since R3.)
// ---------------------------------------------------------------------------
__device__ __forceinline__ float x0_of(unsigned long long p) {
    float di = (float)(unsigned)p;
    float dq = (float)(unsigned)(p >> 32);
    return di * rsqrtf(fmaxf(dq, 1.0f));
}

__global__ void k_scatter1(const int* __restrict__ src, const int* __restrict__ dst, int E) {
    int i = blockIdx.x * blockDim.x + threadIdx.x;
    int base = i << 3;
    if (base + 7 < E) {
        int4 s0 = *reinterpret_cast<const int4*>(src + base);
        int4 s1 = *reinterpret_cast<const int4*>(src + base + 4);
        int4 d0 = *reinterpret_cast<const int4*>(dst + base);
        int4 d1 = *reinterpret_cast<const int4*>(dst + base + 4);
        cudaGridDependencySynchronize();   // wait: k_deg complete (deg + agg1=0)
        float v0 = x0_of(__ldg(&g_deg[s0.x]));
        float v1 = x0_of(__ldg(&g_deg[s0.y]));
        float v2 = x0_of(__ldg(&g_deg[s0.z]));
        float v3 = x0_of(__ldg(&g_deg[s0.w]));
        float v4 = x0_of(__ldg(&g_deg[s1.x]));
        float v5 = x0_of(__ldg(&g_deg[s1.y]));
        float v6 = x0_of(__ldg(&g_deg[s1.z]));
        float v7 = x0_of(__ldg(&g_deg[s1.w]));
        red_f32(&g_agg1[d0.x], v0); red_f32(&g_agg1[d0.y], v1);
        red_f32(&g_agg1[d0.z], v2); red_f32(&g_agg1[d0.w], v3);
        red_f32(&g_agg1[d1.x], v4); red_f32(&g_agg1[d1.y], v5);
        red_f32(&g_agg1[d1.z], v6); red_f32(&g_agg1[d1.w], v7);
    } else {
        cudaGridDependencySynchronize();
        for (int e = base; e < E; ++e)
            red_f32(&g_agg1[dst[e]], x0_of(__ldg(&g_deg[src[e]])));
    }
}

// ---------------------------------------------------------------------------
// K3: t = agg1 * isi * iso — vectorized 4 nodes/thread.
//     Zeroes A and pool BEFORE the dependency sync (independent of upstream).
// ---------------------------------------------------------------------------
__global__ void k_t(int N) {
    int i = blockIdx.x * blockDim.x + threadIdx.x;
    int base = i << 2;
    if (i < GG) g_pool[i] = make_float2(0.f, 0.f);        // untouched upstream
    if (base + 3 < N) {                                   // untouched upstream
        *reinterpret_cast<float4*>(g_A + base) = make_float4(0.f, 0.f, 0.f, 0.f);
    } else {
        for (int n = base; n < N; ++n) g_A[n] = 0.0f;
    }
    cudaGridDependencySynchronize();                      // wait: k_scatter1 done
    if (base + 3 < N) {
        ulonglong2 p01 = *reinterpret_cast<const ulonglong2*>(g_deg + base);
        ulonglong2 p23 = *reinterpret_cast<const ulonglong2*>(g_deg + base + 2);
        float4 a = *reinterpret_cast<const float4*>(g_agg1 + base);
        float4 r;
        r.x = a.x * rsqrtf(fmaxf((float)(unsigned)p01.x, 1.0f)) * rsqrtf(fmaxf((float)(unsigned)(p01.x >> 32), 1.0f));
        r.y = a.y * rsqrtf(fmaxf((float)(unsigned)p01.y, 1.0f)) * rsqrtf(fmaxf((float)(unsigned)(p01.y >> 32), 1.0f));
        r.z = a.z * rsqrtf(fmaxf((float)(unsigned)p23.x, 1.0f)) * rsqrtf(fmaxf((float)(unsigned)(p23.x >> 32), 1.0f));
        r.w = a.w * rsqrtf(fmaxf((float)(unsigned)p23.y, 1.0f)) * rsqrtf(fmaxf((float)(unsigned)(p23.y >> 32), 1.0f));
        *reinterpret_cast<float4*>(g_t + base) = r;
    } else {
        for (int n = base; n < N; ++n) {
            unsigned long long p = g_deg[n];
            g_t[n] = g_agg1[n]
                   * rsqrtf(fmaxf((float)(unsigned)p, 1.0f))
                   * rsqrtf(fmaxf((float)(unsigned)(p >> 32), 1.0f));
        }
    }
}

// ---------------------------------------------------------------------------
// K4: layer-2 scalar scatter  A[dst] += t[src]. 8 edges / thread. (Frozen.)
// ---------------------------------------------------------------------------
__global__ void k_scatter2(const int* __restrict__ src, const int* __restrict__ dst, int E) {
    int i = blockIdx.x * blockDim.x + threadIdx.x;
    int base = i << 3;
    if (base + 7 < E) {
        int4 s0 = *reinterpret_cast<const int4*>(src + base);
        int4 s1 = *reinterpret_cast<const int4*>(src + base + 4);
        int4 d0 = *reinterpret_cast<const int4*>(dst + base);
        int4 d1 = *reinterpret_cast<const int4*>(dst + base + 4);
        cudaGridDependencySynchronize();   // wait: k_t complete (t and A=0)
        float v0 = __ldg(&g_t[s0.x]);
        float v1 = __ldg(&g_t[s0.y]);
        float v2 = __ldg(&g_t[s0.z]);
        float v3 = __ldg(&g_t[s0.w]);
        float v4 = __ldg(&g_t[s1.x]);
        float v5 = __ldg(&g_t[s1.y]);
        float v6 = __ldg(&g_t[s1.z]);
        float v7 = __ldg(&g_t[s1.w]);
        red_f32(&g_A[d0.x], v0); red_f32(&g_A[d0.y], v1);
        red_f32(&g_A[d0.z], v2); red_f32(&g_A[d0.w], v3);
        red_f32(&g_A[d1.x], v4); red_f32(&g_A[d1.y], v5);
        red_f32(&g_A[d1.z], v6); red_f32(&g_A[d1.w], v7);
    } else {
        cudaGridDependencySynchronize();
        for (int e = base; e < E; ++e)
            red_f32(&g_A[dst[e]], __ldg(&g_t[src[e]]));
    }
}

// ---------------------------------------------------------------------------
// K5: pooling, 4 nodes/thread, red.v2 {S, cnt} — one RED per uniform warp.
// ---------------------------------------------------------------------------
__global__ void k_pool(const int* __restrict__ gid, int N) {
    int i = blockIdx.x * blockDim.x + threadIdx.x;
    int base = i << 2;
    bool full = (base + 3 < N);
    int4 g4 = make_int4(-1, -1, -1, -1);
    if (full) g4 = *reinterpret_cast<const int4*>(gid + base);   // input, pre-sync
    cudaGridDependencySynchronize();       // wait: k_scatter2 complete

    float u0 = 0.f, u1 = 0.f, u2 = 0.f, u3 = 0.f;
    if (full) {
        ulonglong2 p01 = *reinterpret_cast<const ulonglong2*>(g_deg + base);
        ulonglong2 p23 = *reinterpret_cast<const ulonglong2*>(g_deg + base + 2);
        float4 a = *reinterpret_cast<const float4*>(g_A + base);
        u0 = a.x * rsqrtf(fmaxf((float)(unsigned)p01.x, 1.0f));
        u1 = a.y * rsqrtf(fmaxf((float)(unsigned)p01.y, 1.0f));
        u2 = a.z * rsqrtf(fmaxf((float)(unsigned)p23.x, 1.0f));
        u3 = a.w * rsqrtf(fmaxf((float)(unsigned)p23.y, 1.0f));
    }

    int  g0  = __shfl_sync(0xffffffffu, g4.x, 0);
    bool uni = __all_sync(0xffffffffu, full && (g4.x == g0) && (g4.w == g0));

    if (uni) {
        float u = (u0 + u1) + (u2 + u3);
#pragma unroll
        for (int o = 16; o > 0; o >>= 1)
            u += __shfl_xor_sync(0xffffffffu, u, o);
        if ((threadIdx.x & 31) == 0)
            red_v2(&g_pool[g0], u, 128.0f);
    } else if (full) {
        // sorted 4-tuple -> run compression (usually 1 run, rarely 2-3)
        int   cg = g4.x;  float s = u0;  float c = 1.0f;
        if (g4.y == cg) { s += u1; c += 1.0f; }
        else { red_v2(&g_pool[cg], s, c); cg = g4.y; s = u1; c = 1.0f; }
        if (g4.z == cg) { s += u2; c += 1.0f; }
        else { red_v2(&g_pool[cg], s, c); cg = g4.z; s = u2; c = 1.0f; }
        if (g4.w == cg) { s += u3; c += 1.0f; }
        else { red_v2(&g_pool[cg], s, c); cg = g4.w; s = u3; c = 1.0f; }
        red_v2(&g_pool[cg], s, c);
    } else {
        // tail: scalar per node
        for (int n = base; n < N; ++n) {
            unsigned long long p = g_deg[n];
            float u = g_A[n] * rsqrtf(fmaxf((float)(unsigned)p, 1.0f));
            red_v2(&g_pool[gid[n]], u, 1.0f);
        }
    }
}

// ---------------------------------------------------------------------------
// K6: out[g][c] = (S_g/max(cnt_g,1)) * rW_c.  rw GEMV before sync (inputs only).
// ---------------------------------------------------------------------------
__global__ void k_final(const float* __restrict__ W1, const float* __restrict__ W2,
                        const float* __restrict__ Wlast, float* __restrict__ out, int G) {
    int t = blockIdx.x * blockDim.x + threadIdx.x;
    int c = t & 7;
    float rw = 0.0f;
#pragma unroll
    for (int k = 0; k < 8; ++k) {
        float q = 0.0f;
#pragma unroll
        for (int j = 0; j < 8; ++j)
            q += fmaxf(__ldg(&W1[j]), 0.0f) * __ldg(&W2[j * 8 + k]);
        rw += fmaxf(q, 0.0f) * __ldg(&Wlast[k * 8 + c]);
    }
    cudaGridDependencySynchronize();       // wait: k_pool complete
    if (t >= G * 8) return;
    float2 p = g_pool[t >> 3];
    out[t] = (p.x / fmaxf(p.y, 1.0f)) * rw;
}

// ---------------------------------------------------------------------------
// kernel_launch — PDL chain; ONE memset (deg only; agg1 zeroed in k_deg).
// Inputs (metadata order): W1[8], W2[64], Wlast[64], src[E], dst[E], graph_ids[N]
// Output: G*C float32
// ---------------------------------------------------------------------------
extern "C" void kernel_launch(void* const* d_in, const int* in_sizes, int n_in,
                              void* d_out, int out_size) {
    const float* W1    = (const float*)d_in[0];
    const float* W2    = (const float*)d_in[1];
    const float* Wlast = (const float*)d_in[2];
    const int*   src   = (const int*)d_in[3];
    const int*   dst   = (const int*)d_in[4];
    const int*   gid   = (const int*)d_in[5];

    int E = in_sizes[3];
    int N = in_sizes[5];
    int G = out_size / 8;
    float* out = (float*)d_out;

    void* pdeg;
    cudaGetSymbolAddress(&pdeg, g_deg);
    cudaMemsetAsync(pdeg, 0, (size_t)N * sizeof(unsigned long long));

    const int TB = 256;
    int nE8 = (E + 7) / 8;
    unsigned gE8 = (unsigned)((nE8 + TB - 1) / TB);
    unsigned gN4 = (unsigned)(((N + 3) / 4 + TB - 1) / TB);
    unsigned gF  = (unsigned)((G * 8 + TB - 1) / TB);

    cudaLaunchAttribute attr[1];
    attr[0].id = cudaLaunchAttributeProgrammaticStreamSerialization;
    attr[0].val.programmaticStreamSerializationAllowed = 1;

    cudaLaunchConfig_t cfg{};
    cfg.blockDim = {TB, 1, 1};
    cfg.attrs = attr;
    cfg.numAttrs = 1;
    cfg.stream = 0;

    cfg.gridDim = {gE8, 1, 1};
    cudaLaunchKernelEx(&cfg, k_deg, src, dst, E, N);
    cudaLaunchKernelEx(&cfg, k_scatter1, src, dst, E);
    cfg.gridDim = {gN4, 1, 1};
    cudaLaunchKernelEx(&cfg, k_t, N);
    cfg.gridDim = {gE8, 1, 1};
    cudaLaunchKernelEx(&cfg, k_scatter2, src, dst, E);
    cfg.gridDim = {gN4, 1, 1};
    cudaLaunchKernelEx(&cfg, k_pool, gid, N);
    cfg.gridDim = {gF, 1, 1};
    cudaLaunchKernelEx(&cfg, k_final, W1, W2, Wlast, out, G);
}